// round 3
// baseline (speedup 1.0000x reference)
#include <cuda_runtime.h>
#include <math.h>

#define NO 2048
#define NI 16
#define NF 4
#define ND 128
#define NN 8
#define ND2 64
#define NT 512

typedef unsigned long long u64;

// SMEM layout (float offsets)
#define OFF_FAC   0        // 16*4*128 = 8192
#define OFF_FEAT  8192     // 2048
#define OFF_W1    10240    // 16384 floats (8192 u64)
#define OFF_W2    26624    // 16384 floats
#define OFF_H     43008    // 8192 floats (h / contribution buffer)
#define OFF_ADD   51200    // 512
#define OFF_B1    51712    // 128
#define OFF_B2    51840    // 128
#define OFF_RED   51968    // 512 floats (final com reduce scratch)
#define OFF_INT   52480
#define SMEM_FLOATS 52480
#define SMEM_INTS   688    // items16 nbr128 count16 cand256 cmask256 flag1 (+pad)
#define SMEM_BYTES  (SMEM_FLOATS*4 + SMEM_INTS*4)

__device__ float g_com_partial[NO];
__device__ unsigned g_counter = 0;

__device__ __forceinline__ float lrelu(float v){ return v >= 0.f ? v : 0.01f*v; }

__device__ __forceinline__ u64 packff(float lo, float hi){
    u64 d; asm("mov.b64 %0, {%1, %2};" : "=l"(d) : "f"(lo), "f"(hi)); return d;
}
__device__ __forceinline__ u64 f2fma(u64 a, u64 b, u64 c){
    u64 d; asm("fma.rn.f32x2 %0, %1, %2, %3;" : "=l"(d) : "l"(a), "l"(b), "l"(c)); return d;
}
__device__ __forceinline__ u64 f2mul(u64 a, u64 b){
    u64 d; asm("mul.rn.f32x2 %0, %1, %2;" : "=l"(d) : "l"(a), "l"(b)); return d;
}
__device__ __forceinline__ float f2red(u64 v){
    float lo, hi; asm("mov.b64 {%0, %1}, %2;" : "=f"(lo), "=f"(hi) : "l"(v));
    return lo + hi;
}

__device__ __forceinline__ void load_f(float* dst, const float* src, int n){
    for (int i = threadIdx.x; i < n; i += NT) dst[i] = src[i];
}
// Pack weight [2K rows][cols] row-major -> dst[k2*cols + d] = {W[2k2][d], W[2k2+1][d]}
__device__ __forceinline__ void load_packed(u64* dst, const float* src, int n, int cshift){
    const int cmask = (1 << cshift) - 1;
    for (int idx = threadIdx.x; idx < n; idx += NT){
        int k2 = idx >> cshift, d = idx & cmask;
        dst[idx] = packff(src[((2*k2) << cshift) + d], src[((2*k2+1) << cshift) + d]);
    }
}

__global__ __launch_bounds__(NT, 1)
void mfgn_kernel(
    const int*   __restrict__ outfit_items,
    const float* __restrict__ items_feature,
    const int*   __restrict__ items_neighbor,
    const float* __restrict__ cf_W1,  const float* __restrict__ cf_b1,
    const float* __restrict__ cf_W2,  const float* __restrict__ cf_b2,
    const float* __restrict__ f2f_W1, const float* __restrict__ f2f_b1,
    const float* __restrict__ f2f_W2, const float* __restrict__ f2f_b2,
    const float* __restrict__ f2i_W1, const float* __restrict__ f2i_b1,
    const float* __restrict__ f2i_W2, const float* __restrict__ f2i_b2,
    const float* __restrict__ i2i_W1, const float* __restrict__ i2i_b1,
    const float* __restrict__ i2i_W2, const float* __restrict__ i2i_b2,
    const float* __restrict__ o2s_W,  const float* __restrict__ o2s_b,
    float* __restrict__ d_out)
{
    extern __shared__ float sm[];
    float* s_fac  = sm + OFF_FAC;   // [item][f][d]
    float* s_feat = sm + OFF_FEAT;  // [item][d]
    u64*   s_W1p  = (u64*)(sm + OFF_W1);
    u64*   s_W2p  = (u64*)(sm + OFF_W2);
    float* s_h    = sm + OFF_H;     // 8192 floats
    float* s_add  = sm + OFF_ADD;
    float* s_b1   = sm + OFF_B1;
    float* s_b2   = sm + OFF_B2;
    float* s_red  = sm + OFF_RED;
    int*   s_items = (int*)(sm + OFF_INT);
    int*   s_nbr   = s_items + NI;
    int*   s_count = s_nbr + NI*NN;
    int*   s_cand  = s_count + NI;           // [16 steps][16 slots]
    float* s_cmask = (float*)(s_cand + 256); // [16][16]
    int*   s_flag  = (int*)(s_cmask + 256);

    const int o    = blockIdx.x;
    const int tid  = threadIdx.x;
    const int w    = tid >> 5;      // 0..15
    const int lane = tid & 31;

    if (tid < NI)    s_items[tid] = outfit_items[o*NI + tid];
    if (tid < NI*NN) s_nbr[tid]   = items_neighbor[o*NI*NN + tid];
    load_f(s_feat, items_feature + (size_t)o*NI*ND, NI*ND);
    __syncthreads();
    if (tid < NI){
        int c = 0;
        #pragma unroll
        for (int s = 0; s < NI; s++) c += (s_items[s] == tid);
        s_count[tid] = c;
    }
    // precompute compacted candidate lists for all 16 steps (warp w -> step w)
    {
        const int i = s_items[w];
        int c = 0; bool v = false;
        if (i >= 0 && lane < NI + NN){
            c = (lane < NI) ? s_items[lane] : s_nbr[i*NN + (lane - NI)];
            v = (c != -1) && (c != i);
        }
        unsigned bal = __ballot_sync(0xffffffffu, v);
        if (lane < 16){ s_cand[w*16 + lane] = 0; s_cmask[w*16 + lane] = 0.f; }
        __syncwarp();
        if (v){
            int pos = __popc(bal & ((1u << lane) - 1));
            s_cand[w*16 + pos] = c;
            s_cmask[w*16 + pos] = 1.f;
        }
    }

    // =============== Phase 1: creat_factors (warp w -> item w) ===============
    for (int f = 0; f < NF; f++){
        __syncthreads();
        load_packed(s_W1p, cf_W1 + f*ND*ND2, (ND/2)*ND2, 6);   // [64 k2][64 d]
        load_packed(s_W2p, cf_W2 + f*ND2*ND, (ND2/2)*ND, 7);   // [32 k2][128 d]
        load_f(s_b1, cf_b1 + f*ND2, ND2);
        load_f(s_b2, cf_b2 + f*ND, ND);
        __syncthreads();
        {
            u64 a0 = 0, a1 = 0;
            #pragma unroll 4
            for (int k2 = 0; k2 < ND/2; k2++){
                u64 x = *(const u64*)&s_feat[w*ND + 2*k2];
                ulonglong2 wv = *(const ulonglong2*)&s_W1p[k2*ND2 + lane*2];
                a0 = f2fma(x, wv.x, a0); a1 = f2fma(x, wv.y, a1);
            }
            s_h[w*ND2 + lane*2+0] = lrelu(f2red(a0) + s_b1[lane*2]);
            s_h[w*ND2 + lane*2+1] = lrelu(f2red(a1) + s_b1[lane*2+1]);
        }
        __syncwarp();
        {
            u64 c0[4] = {0,0,0,0};
            #pragma unroll 4
            for (int k2 = 0; k2 < ND2/2; k2++){
                u64 h = *(const u64*)&s_h[w*ND2 + 2*k2];
                ulonglong2 wa = *(const ulonglong2*)&s_W2p[k2*ND + lane*4];
                ulonglong2 wb = *(const ulonglong2*)&s_W2p[k2*ND + lane*4 + 2];
                c0[0]=f2fma(h,wa.x,c0[0]); c0[1]=f2fma(h,wa.y,c0[1]);
                c0[2]=f2fma(h,wb.x,c0[2]); c0[3]=f2fma(h,wb.y,c0[3]);
            }
            #pragma unroll
            for (int j = 0; j < 4; j++)
                s_fac[(w*NF + f)*ND + lane*4 + j] = lrelu(f2red(c0[j]) + s_b2[lane*4+j]);
        }
        __syncwarp();
    }

    // =============== Phase 2: inter_factors (warp w -> cand slot w, 4 factors) ===============
    __syncthreads();
    load_packed(s_W1p, f2f_W1, (ND/2)*ND, 7);
    load_packed(s_W2p, f2f_W2, (ND/2)*ND, 7);
    load_f(s_b1, f2f_b1, ND);
    load_f(s_b2, f2f_b2, ND);
    __syncthreads();
    for (int step = 0; step < NI; step++){
        const int i = s_items[step];
        if (i < 0) continue;   // uniform across block

        const int   cc = s_cand[step*16 + w];
        const float m  = s_cmask[step*16 + w];
        const float* xb = s_fac + cc*NF*ND;
        const float* tb = s_fac + i*NF*ND;

        // layer 1: rows = 4 factors, outputs d = lane*4..+3
        u64 acc[4][4];
        #pragma unroll
        for (int r = 0; r < 4; r++)
            #pragma unroll
            for (int j = 0; j < 4; j++) acc[r][j] = 0;
        #pragma unroll 2
        for (int k2 = 0; k2 < ND/2; k2++){
            ulonglong2 wa = *(const ulonglong2*)&s_W1p[k2*ND + lane*4];
            ulonglong2 wb = *(const ulonglong2*)&s_W1p[k2*ND + lane*4 + 2];
            #pragma unroll
            for (int f = 0; f < NF; f++){
                u64 t  = *(const u64*)&tb[f*ND + 2*k2];
                u64 x  = *(const u64*)&xb[f*ND + 2*k2];
                u64 tx = f2mul(t, x);
                acc[f][0] = f2fma(tx, wa.x, acc[f][0]);
                acc[f][1] = f2fma(tx, wa.y, acc[f][1]);
                acc[f][2] = f2fma(tx, wb.x, acc[f][2]);
                acc[f][3] = f2fma(tx, wb.y, acc[f][3]);
            }
        }
        #pragma unroll
        for (int r = 0; r < 4; r++)
            #pragma unroll
            for (int j = 0; j < 4; j++)
                s_h[w*512 + r*ND + lane*4 + j] = lrelu(f2red(acc[r][j]) + s_b1[lane*4+j]);
        __syncwarp();

        // layer 2
        u64 acc2[4][4];
        #pragma unroll
        for (int r = 0; r < 4; r++)
            #pragma unroll
            for (int j = 0; j < 4; j++) acc2[r][j] = 0;
        #pragma unroll 2
        for (int k2 = 0; k2 < ND/2; k2++){
            ulonglong2 wa = *(const ulonglong2*)&s_W2p[k2*ND + lane*4];
            ulonglong2 wb = *(const ulonglong2*)&s_W2p[k2*ND + lane*4 + 2];
            #pragma unroll
            for (int r = 0; r < 4; r++){
                u64 h = *(const u64*)&s_h[w*512 + r*ND + 2*k2];
                acc2[r][0] = f2fma(h, wa.x, acc2[r][0]);
                acc2[r][1] = f2fma(h, wa.y, acc2[r][1]);
                acc2[r][2] = f2fma(h, wb.x, acc2[r][2]);
                acc2[r][3] = f2fma(h, wb.y, acc2[r][3]);
            }
        }
        __syncwarp();   // all lanes done reading h rows before overwrite
        #pragma unroll
        for (int f = 0; f < NF; f++)
            #pragma unroll
            for (int j = 0; j < 4; j++)
                s_h[w*512 + f*ND + lane*4 + j] =
                    m * lrelu(f2red(acc2[f][j]) + s_b2[lane*4+j]);
        __syncthreads();
        {
            float s = 0.f;
            #pragma unroll
            for (int ww = 0; ww < 16; ww++) s += s_h[ww*512 + tid];
            s_fac[i*NF*ND + tid] += s;
        }
        __syncthreads();
    }

    // =============== com loss partial (warp w -> position w) ===============
    {
        float csum = 0.f;
        if (s_items[w] != -1){
            const float* fp = s_fac + w*NF*ND;
            #pragma unroll
            for (int a = 0; a < NF; a++)
                #pragma unroll
                for (int b = 0; b < NF; b++){
                    float p = 0.f;
                    #pragma unroll
                    for (int k = 0; k < 4; k++)
                        p += fp[a*ND + lane + 32*k] * fp[b*ND + lane + 32*k];
                    #pragma unroll
                    for (int off2 = 16; off2; off2 >>= 1)
                        p += __shfl_xor_sync(0xffffffffu, p, off2);
                    float gg = p - (a == b ? 1.f : 0.f);
                    csum += gg*gg;
                }
        }
        if (lane == 0) s_add[w] = csum;
    }

    // =============== Phase 3: infer_items (warp w -> item w, 4 factors) ===============
    __syncthreads();
    load_packed(s_W1p, f2i_W1, (ND/2)*ND, 7);
    load_packed(s_W2p, f2i_W2, (ND/2)*ND, 7);
    load_f(s_b1, f2i_b1, ND);
    load_f(s_b2, f2i_b2, ND);
    __syncthreads();
    {
        u64 acc[4][4];
        #pragma unroll
        for (int r = 0; r < 4; r++)
            #pragma unroll
            for (int j = 0; j < 4; j++) acc[r][j] = 0;
        #pragma unroll 2
        for (int k2 = 0; k2 < ND/2; k2++){
            ulonglong2 wa = *(const ulonglong2*)&s_W1p[k2*ND + lane*4];
            ulonglong2 wb = *(const ulonglong2*)&s_W1p[k2*ND + lane*4 + 2];
            #pragma unroll
            for (int f = 0; f < NF; f++){
                u64 x = *(const u64*)&s_fac[(w*NF+f)*ND + 2*k2];
                acc[f][0] = f2fma(x, wa.x, acc[f][0]);
                acc[f][1] = f2fma(x, wa.y, acc[f][1]);
                acc[f][2] = f2fma(x, wb.x, acc[f][2]);
                acc[f][3] = f2fma(x, wb.y, acc[f][3]);
            }
        }
        #pragma unroll
        for (int r = 0; r < 4; r++)
            #pragma unroll
            for (int j = 0; j < 4; j++)
                s_h[w*512 + r*ND + lane*4 + j] = lrelu(f2red(acc[r][j]) + s_b1[lane*4+j]);
        __syncwarp();
        u64 acc2[4][4];
        #pragma unroll
        for (int r = 0; r < 4; r++)
            #pragma unroll
            for (int j = 0; j < 4; j++) acc2[r][j] = 0;
        #pragma unroll 2
        for (int k2 = 0; k2 < ND/2; k2++){
            ulonglong2 wa = *(const ulonglong2*)&s_W2p[k2*ND + lane*4];
            ulonglong2 wb = *(const ulonglong2*)&s_W2p[k2*ND + lane*4 + 2];
            #pragma unroll
            for (int r = 0; r < 4; r++){
                u64 h = *(const u64*)&s_h[w*512 + r*ND + 2*k2];
                acc2[r][0] = f2fma(h, wa.x, acc2[r][0]);
                acc2[r][1] = f2fma(h, wa.y, acc2[r][1]);
                acc2[r][2] = f2fma(h, wb.x, acc2[r][2]);
                acc2[r][3] = f2fma(h, wb.y, acc2[r][3]);
            }
        }
        float cnt = (float)s_count[w];
        #pragma unroll
        for (int j = 0; j < 4; j++){
            float b = s_b2[lane*4+j];
            float gs = 0.f;
            #pragma unroll
            for (int f = 0; f < NF; f++)
                gs += lrelu(f2red(acc2[f][j]) + b);
            s_feat[w*ND + lane*4 + j] += cnt * gs;
        }
    }

    // =============== Phase 4: inter_items (warp w -> source slot w) ===============
    __syncthreads();
    load_packed(s_W1p, i2i_W1, (ND/2)*ND, 7);
    load_packed(s_W2p, i2i_W2, (ND/2)*ND, 7);
    load_f(s_b1, i2i_b1, ND);
    load_f(s_b2, i2i_b2, ND);
    __syncthreads();
    for (int step = 0; step < NI; step++){
        const int i = s_items[step];
        if (i < 0) continue;
        const int   sv = s_items[w];
        const float m  = (sv != -1 && sv != i) ? 1.f : 0.f;
        const int   jc = sv < 0 ? 0 : sv;

        u64 a[4] = {0,0,0,0};
        #pragma unroll 4
        for (int k2 = 0; k2 < ND/2; k2++){
            u64 x = *(const u64*)&s_feat[jc*ND + 2*k2];
            ulonglong2 wa = *(const ulonglong2*)&s_W1p[k2*ND + lane*4];
            ulonglong2 wb = *(const ulonglong2*)&s_W1p[k2*ND + lane*4 + 2];
            a[0]=f2fma(x,wa.x,a[0]); a[1]=f2fma(x,wa.y,a[1]);
            a[2]=f2fma(x,wb.x,a[2]); a[3]=f2fma(x,wb.y,a[3]);
        }
        #pragma unroll
        for (int j = 0; j < 4; j++)
            s_h[w*ND + lane*4 + j] = lrelu(f2red(a[j]) + s_b1[lane*4+j]);
        __syncwarp();
        u64 c0[4] = {0,0,0,0};
        #pragma unroll 4
        for (int k2 = 0; k2 < ND/2; k2++){
            u64 h = *(const u64*)&s_h[w*ND + 2*k2];
            ulonglong2 wa = *(const ulonglong2*)&s_W2p[k2*ND + lane*4];
            ulonglong2 wb = *(const ulonglong2*)&s_W2p[k2*ND + lane*4 + 2];
            c0[0]=f2fma(h,wa.x,c0[0]); c0[1]=f2fma(h,wa.y,c0[1]);
            c0[2]=f2fma(h,wb.x,c0[2]); c0[3]=f2fma(h,wb.y,c0[3]);
        }
        __syncwarp();
        #pragma unroll
        for (int j = 0; j < 4; j++)
            s_h[w*ND + lane*4 + j] = m * lrelu(f2red(c0[j]) + s_b2[lane*4+j]);
        __syncthreads();
        if (tid < ND){
            float s = 0.f;
            #pragma unroll
            for (int ww = 0; ww < 16; ww++) s += s_h[ww*ND + tid];
            s_feat[i*ND + tid] += s;
        }
        __syncthreads();
    }

    // =============== Phase 5: score + com partial store ===============
    if (w == 0){
        float4 ov = make_float4(0.f,0.f,0.f,0.f);
        #pragma unroll
        for (int s = 0; s < NI; s++){
            int it = s_items[s];
            if (it >= 0){
                float4 fv = *(float4*)&s_feat[it*ND + lane*4];
                ov.x += fv.x; ov.y += fv.y; ov.z += fv.z; ov.w += fv.w;
            }
        }
        const float4 wv = *(const float4*)&o2s_W[lane*4];
        float p = ov.x*wv.x + ov.y*wv.y + ov.z*wv.z + ov.w*wv.w;
        #pragma unroll
        for (int off2 = 16; off2; off2 >>= 1)
            p += __shfl_xor_sync(0xffffffffu, p, off2);
        if (lane == 0) d_out[o] = 1.f / (1.f + expf(-(p + o2s_b[0])));
    }
    if (tid == 0){
        float tot = 0.f;
        #pragma unroll
        for (int ww = 0; ww < 16; ww++) tot += s_add[ww];
        g_com_partial[o] = tot;
        __threadfence();
        unsigned r = atomicAdd(&g_counter, 1u);
        *s_flag = (r == (unsigned)(NO - 1)) ? 1 : 0;
    }
    __syncthreads();
    if (*s_flag){
        __threadfence();  // acquire: all other CTAs' partials visible
        float s = 0.f;
        #pragma unroll
        for (int c = 0; c < NO/NT; c++) s += g_com_partial[tid + c*NT];
        s_red[tid] = s;
        __syncthreads();
        for (int st = NT/2; st > 0; st >>= 1){
            if (tid < st) s_red[tid] += s_red[tid + st];
            __syncthreads();
        }
        if (tid == 0){
            d_out[NO] = s_red[0] / (float)NO;
            g_counter = 0;   // reset for next launch / replay
        }
    }
}

extern "C" void kernel_launch(void* const* d_in, const int* in_sizes, int n_in,
                              void* d_out, int out_size)
{
    (void)in_sizes; (void)n_in; (void)out_size;
    cudaFuncSetAttribute(mfgn_kernel, cudaFuncAttributeMaxDynamicSharedMemorySize, SMEM_BYTES);

    const int*   outfit_items   = (const int*)  d_in[0];
    const float* items_feature  = (const float*)d_in[1];
    const int*   items_neighbor = (const int*)  d_in[2];
    const float* cf_W1  = (const float*)d_in[4];
    const float* cf_b1  = (const float*)d_in[5];
    const float* cf_W2  = (const float*)d_in[6];
    const float* cf_b2  = (const float*)d_in[7];
    const float* f2f_W1 = (const float*)d_in[8];
    const float* f2f_b1 = (const float*)d_in[9];
    const float* f2f_W2 = (const float*)d_in[10];
    const float* f2f_b2 = (const float*)d_in[11];
    const float* f2i_W1 = (const float*)d_in[12];
    const float* f2i_b1 = (const float*)d_in[13];
    const float* f2i_W2 = (const float*)d_in[14];
    const float* f2i_b2 = (const float*)d_in[15];
    const float* i2i_W1 = (const float*)d_in[16];
    const float* i2i_b1 = (const float*)d_in[17];
    const float* i2i_W2 = (const float*)d_in[18];
    const float* i2i_b2 = (const float*)d_in[19];
    const float* o2s_W  = (const float*)d_in[20];
    const float* o2s_b  = (const float*)d_in[21];

    mfgn_kernel<<<NO, NT, SMEM_BYTES>>>(
        outfit_items, items_feature, items_neighbor,
        cf_W1, cf_b1, cf_W2, cf_b2,
        f2f_W1, f2f_b1, f2f_W2, f2f_b2,
        f2i_W1, f2i_b1, f2i_W2, f2i_b2,
        i2i_W1, i2i_b1, i2i_W2, i2i_b2,
        o2s_W, o2s_b, (float*)d_out);
}